// round 5
// baseline (speedup 1.0000x reference)
#include <cuda_runtime.h>

#define IMG    4096
#define TW     128               // tile width (x) = threads per CTA
#define TH     32                // tile height (y) = outputs per thread (KY)
#define RAWW   (TW + 15)         // 143 raw cols: gx0-8 .. gx0+TW+6
#define ROWSM  (TH + 14)         // 46 rows:     gy0-7 .. gy0+TH+6
#define STRIDE 145               // odd -> conflict-free column walks
#define SEG0   72                // prefix segment split (cols 1..72 | 73..143)

__global__ __launch_bounds__(128, 5) void meanconv_sweep_kernel(
    const float* __restrict__ x,
    const float* __restrict__ mask,
    float* __restrict__ out)
{
    __shared__ float S[ROWSM * STRIDE];   // 46*145*4 = 26.7 KB

    const int t   = threadIdx.x;          // 0..127
    const int gx0 = blockIdx.x * TW;
    const int gy0 = blockIdx.y * TH;

    // ---- Load clamped raw tile (replicate padding == index clamp) ----
    for (int idx = t; idx < ROWSM * RAWW; idx += TW) {
        int r = idx / RAWW;
        int c = idx - r * RAWW;
        int gy = gy0 - 7 + r; gy = min(max(gy, 0), IMG - 1);
        int gx = gx0 - 8 + c; gx = min(max(gx, 0), IMG - 1);
        S[r * STRIDE + 1 + c] = x[gy * IMG + gx];
    }
    __syncthreads();

    // ---- Horizontal prefix per row, 2 segments (92 threads) ----
    if (t < 2 * ROWSM) {
        const int seg = t / ROWSM;           // 0 or 1
        const int row = t - seg * ROWSM;
        float* rp = &S[row * STRIDE];
        if (seg == 0) {
            rp[0] = 0.0f;
            float acc = 0.0f;
            #pragma unroll
            for (int c = 1; c <= SEG0; c++) { acc += rp[c]; rp[c] = acc; }
        } else {
            float acc = 0.0f;
            #pragma unroll
            for (int c = SEG0 + 1; c < RAWW + 1; c++) { acc += rp[c]; rp[c] = acc; }
        }
    }
    __syncthreads();

    // ---- Fix-up: add seg0 total to seg1 entries (46 threads) ----
    if (t < ROWSM) {
        float* rp = &S[t * STRIDE];
        const float tot = rp[SEG0];
        #pragma unroll 8
        for (int c = SEG0 + 1; c < RAWW + 1; c++) rp[c] += tot;
    }
    __syncthreads();

    // ---- Unified row sweep: 7 parallel sliding box chains per thread ----
    // rs_p(r) = P[r][t+9+p] - P[r][t+8-p]  (horizontal window sum, width 2p+1)
    const float* Pt = &S[t + 8];

    // w[p] = 1 / (7*(2p+1)^2)
    const float W1 = 1.0f/63.0f,   W2 = 1.0f/175.0f, W3 = 1.0f/343.0f,
                W4 = 1.0f/567.0f,  W5 = 1.0f/847.0f, W6 = 1.0f/1183.0f,
                W7 = 1.0f/1575.0f;

    float ring[63];                       // rings for p=1..7, offsets below
    const int ROFF[8] = {0, 0, 3, 8, 15, 24, 35, 48};
    float B[7];

    // Init: windows centered at j=0 (rows 7-p .. 7+p)
    #pragma unroll
    for (int p = 1; p <= 7; p++) {
        float b = 0.0f;
        #pragma unroll
        for (int i = 0; i <= 2 * p; i++) {
            const int r = 7 - p + i;
            float rs = Pt[r * STRIDE + 1 + p] - Pt[r * STRIDE - p];
            ring[ROFF[p] + i] = rs;
            b += rs;
        }
        B[p - 1] = b;
    }
    {
        float acc =        W1 * B[0];
        acc = fmaf(W2, B[1], acc); acc = fmaf(W3, B[2], acc);
        acc = fmaf(W4, B[3], acc); acc = fmaf(W5, B[4], acc);
        acc = fmaf(W6, B[5], acc); acc = fmaf(W7, B[6], acc);
        const int g = gy0 * IMG + gx0 + t;
        out[g] = acc * mask[g];
    }

    // Steady state: fully unrolled so ring slots & addresses are static
    #pragma unroll
    for (int j = 1; j < TH; j++) {
        #pragma unroll
        for (int p = 1; p <= 7; p++) {
            const int r = j + 7 + p;
            float rs = Pt[r * STRIDE + 1 + p] - Pt[r * STRIDE - p];
            const int slot = ROFF[p] + (j - 1) % (2 * p + 1);  // compile-time
            float old = ring[slot];
            ring[slot] = rs;
            B[p - 1] += rs - old;
        }
        float acc =        W1 * B[0];
        acc = fmaf(W2, B[1], acc); acc = fmaf(W3, B[2], acc);
        acc = fmaf(W4, B[3], acc); acc = fmaf(W5, B[4], acc);
        acc = fmaf(W6, B[5], acc); acc = fmaf(W7, B[6], acc);
        const int g = (gy0 + j) * IMG + gx0 + t;
        out[g] = acc * mask[g];
    }
}

extern "C" void kernel_launch(void* const* d_in, const int* in_sizes, int n_in,
                              void* d_out, int out_size)
{
    (void)n_in; (void)in_sizes; (void)out_size;
    const float* x    = (const float*)d_in[0];
    const float* mask = (const float*)d_in[1];
    float* out        = (float*)d_out;

    dim3 grid(IMG / TW, IMG / TH);   // 32 x 128 tiles
    meanconv_sweep_kernel<<<grid, TW>>>(x, mask, out);
}